// round 1
// baseline (speedup 1.0000x reference)
#include <cuda_runtime.h>
#include <math.h>

#define NB 8
#define NC 512
#define NC8 64
#define NH 64
#define NW 64
#define NHW 4096

// Scratch (allocation-free rule: __device__ globals)
__device__ float g_pq[NB * NC8 * NHW];        // 8 MB
__device__ float g_pk[NB * NC8 * NHW];        // 8 MB
__device__ float g_pv[NB * NC * NHW];         // 64 MB
__device__ float g_att[NB * NH * NW * 128];   // 16 MB

// ---------------------------------------------------------------------------
// Projection GEMM: P[b,m,n] = sum_k Wm[m,k] * X[b,k,n] + bias[m]
// K = 512, N = 4096. Tile 64x128x16, 256 threads, 4x8 per thread.
// which: 0 -> g_pq, 1 -> g_pk, 2 -> g_pv
// ---------------------------------------------------------------------------
__global__ __launch_bounds__(256) void proj_gemm(
    const float* __restrict__ Wm, const float* __restrict__ bias,
    const float* __restrict__ X, int M, int which) {
  float* P = (which == 0) ? g_pq : (which == 1) ? g_pk : g_pv;
  const int b = blockIdx.z;
  const int n0 = blockIdx.x * 128;
  const int m0 = blockIdx.y * 64;
  __shared__ float As[16][64];
  __shared__ float Bs[16][128];
  const int tid = threadIdx.x;
  const float* Xb = X + (size_t)b * NC * NHW;

  float acc[4][8];
#pragma unroll
  for (int i = 0; i < 4; i++)
#pragma unroll
    for (int j = 0; j < 8; j++) acc[i][j] = 0.f;

  const int mB = (tid >> 4) * 4;
  const int nB = (tid & 15) * 8;
  const int am = tid >> 2;
  const int ak = (tid & 3) * 4;
  const int bk = tid >> 4;
  const int bn = (tid & 15) * 8;

  for (int k0 = 0; k0 < NC; k0 += 16) {
    float4 a4 = *(const float4*)(Wm + (size_t)(m0 + am) * NC + k0 + ak);
    As[ak + 0][am] = a4.x;
    As[ak + 1][am] = a4.y;
    As[ak + 2][am] = a4.z;
    As[ak + 3][am] = a4.w;
    const float* bp = Xb + (size_t)(k0 + bk) * NHW + n0 + bn;
    *(float4*)&Bs[bk][bn] = *(const float4*)bp;
    *(float4*)&Bs[bk][bn + 4] = *(const float4*)(bp + 4);
    __syncthreads();
#pragma unroll
    for (int k = 0; k < 16; k++) {
      float av[4], bv[8];
#pragma unroll
      for (int i = 0; i < 4; i++) av[i] = As[k][mB + i];
#pragma unroll
      for (int j = 0; j < 8; j++) bv[j] = Bs[k][nB + j];
#pragma unroll
      for (int i = 0; i < 4; i++)
#pragma unroll
        for (int j = 0; j < 8; j++) acc[i][j] += av[i] * bv[j];
    }
    __syncthreads();
  }

  float* Pb = P + (size_t)b * M * NHW;
#pragma unroll
  for (int i = 0; i < 4; i++) {
    float bb = bias[m0 + mB + i];
    float* o = Pb + (size_t)(m0 + mB + i) * NHW + n0 + nB;
    float4 r0, r1;
    r0.x = acc[i][0] + bb; r0.y = acc[i][1] + bb;
    r0.z = acc[i][2] + bb; r0.w = acc[i][3] + bb;
    r1.x = acc[i][4] + bb; r1.y = acc[i][5] + bb;
    r1.z = acc[i][6] + bb; r1.w = acc[i][7] + bb;
    *(float4*)o = r0;
    *(float4*)(o + 4) = r1;
  }
}

// ---------------------------------------------------------------------------
// eH logits: per (b, w). E[h,k] = sum_c pq[b,c,h,w] * pk[b,c,k,w], diag -inf.
// Written to att[b,h,w,0:64].
// ---------------------------------------------------------------------------
__global__ __launch_bounds__(256) void logits_h_kernel() {
  const int w = blockIdx.x, b = blockIdx.y;
  __shared__ float Q[64][65];
  __shared__ float Kt[64][65];
  const int tid = threadIdx.x;
  const float* pqb = g_pq + (size_t)b * NC8 * NHW;
  const float* pkb = g_pk + (size_t)b * NC8 * NHW;
  for (int i = tid; i < 4096; i += 256) {
    int c = i >> 6, x = i & 63;
    int idx = (c * 64 + x) * 64 + w;
    Q[c][x] = pqb[idx];
    Kt[c][x] = pkb[idx];
  }
  __syncthreads();
  const int th = (tid >> 4) * 4;
  const int tk = (tid & 15) * 4;
  float acc[4][4] = {};
#pragma unroll 4
  for (int c = 0; c < 64; c++) {
    float qv[4], kv[4];
#pragma unroll
    for (int i = 0; i < 4; i++) qv[i] = Q[c][th + i];
#pragma unroll
    for (int j = 0; j < 4; j++) kv[j] = Kt[c][tk + j];
#pragma unroll
    for (int i = 0; i < 4; i++)
#pragma unroll
      for (int j = 0; j < 4; j++) acc[i][j] += qv[i] * kv[j];
  }
#pragma unroll
  for (int i = 0; i < 4; i++) {
    int h = th + i;
#pragma unroll
    for (int j = 0; j < 4; j++) {
      int k = tk + j;
      float e = (h == k) ? -INFINITY : acc[i][j];
      g_att[(((size_t)(b * 64 + h) * 64 + w) << 7) + k] = e;
    }
  }
}

// ---------------------------------------------------------------------------
// eW logits: per (b, h). E[w,k] = sum_c pq[b,c,h,w] * pk[b,c,h,k].
// Written to att[b,h,w,64:128].
// ---------------------------------------------------------------------------
__global__ __launch_bounds__(256) void logits_w_kernel() {
  const int h = blockIdx.x, b = blockIdx.y;
  __shared__ float Q[64][65];
  __shared__ float Kt[64][65];
  const int tid = threadIdx.x;
  const float* pqb = g_pq + (size_t)b * NC8 * NHW;
  const float* pkb = g_pk + (size_t)b * NC8 * NHW;
  for (int i = tid; i < 4096; i += 256) {
    int c = i >> 6, x = i & 63;
    int idx = (c * 64 + h) * 64 + x;
    Q[c][x] = pqb[idx];
    Kt[c][x] = pkb[idx];
  }
  __syncthreads();
  const int tw = (tid >> 4) * 4;
  const int tk = (tid & 15) * 4;
  float acc[4][4] = {};
#pragma unroll 4
  for (int c = 0; c < 64; c++) {
    float qv[4], kv[4];
#pragma unroll
    for (int i = 0; i < 4; i++) qv[i] = Q[c][tw + i];
#pragma unroll
    for (int j = 0; j < 4; j++) kv[j] = Kt[c][tk + j];
#pragma unroll
    for (int i = 0; i < 4; i++)
#pragma unroll
      for (int j = 0; j < 4; j++) acc[i][j] += qv[i] * kv[j];
  }
#pragma unroll
  for (int i = 0; i < 4; i++) {
    int w = tw + i;
#pragma unroll
    for (int j = 0; j < 4; j++) {
      g_att[(((size_t)(b * 64 + h) * 64 + w) << 7) + 64 + tk + j] = acc[i][j];
    }
  }
}

// ---------------------------------------------------------------------------
// Softmax over the 128 concatenated logits, one warp per pixel.
// ---------------------------------------------------------------------------
__global__ __launch_bounds__(256) void softmax_kernel() {
  const int row = (blockIdx.x * 256 + threadIdx.x) >> 5;
  const int lane = threadIdx.x & 31;
  float4* rp = (float4*)(g_att + (size_t)row * 128);
  float4 v = rp[lane];
  float m = fmaxf(fmaxf(v.x, v.y), fmaxf(v.z, v.w));
#pragma unroll
  for (int o = 16; o; o >>= 1) m = fmaxf(m, __shfl_xor_sync(0xffffffffu, m, o));
  v.x = expf(v.x - m);
  v.y = expf(v.y - m);
  v.z = expf(v.z - m);
  v.w = expf(v.w - m);
  float s = v.x + v.y + v.z + v.w;
#pragma unroll
  for (int o = 16; o; o >>= 1) s += __shfl_xor_sync(0xffffffffu, s, o);
  float inv = 1.f / s;
  v.x *= inv; v.y *= inv; v.z *= inv; v.w *= inv;
  rp[lane] = v;
}

// ---------------------------------------------------------------------------
// outH: per (b, w). out[c,h] = sum_k pv[b,c,k,w] * aH[b,h,w,k]  (unscaled)
// ---------------------------------------------------------------------------
__global__ __launch_bounds__(256) void out_h_kernel(float* __restrict__ out) {
  const int w = blockIdx.x, b = blockIdx.y;
  __shared__ float A[64][65];    // A[h][k]
  __shared__ float Pv[64][65];   // Pv[c][k]
  const int tid = threadIdx.x;
  for (int i = tid; i < 4096; i += 256) {
    int h = i >> 6, k = i & 63;
    A[h][k] = g_att[(((size_t)(b * 64 + h) * 64 + w) << 7) + k];
  }
  __syncthreads();
  const int tc = (tid >> 4) * 4;
  const int th = (tid & 15) * 4;
  const float* pvb = g_pv + (size_t)b * NC * NHW;
  float* outb = out + (size_t)b * NC * NHW;
  for (int c0 = 0; c0 < NC; c0 += 64) {
    for (int i = tid; i < 4096; i += 256) {
      int cc = i >> 6, k = i & 63;
      Pv[cc][k] = pvb[(size_t)((c0 + cc) * 64 + k) * 64 + w];
    }
    __syncthreads();
    float acc[4][4] = {};
#pragma unroll 4
    for (int k = 0; k < 64; k++) {
      float pvv[4], av[4];
#pragma unroll
      for (int i = 0; i < 4; i++) pvv[i] = Pv[tc + i][k];
#pragma unroll
      for (int j = 0; j < 4; j++) av[j] = A[th + j][k];
#pragma unroll
      for (int i = 0; i < 4; i++)
#pragma unroll
        for (int j = 0; j < 4; j++) acc[i][j] += pvv[i] * av[j];
    }
#pragma unroll
    for (int i = 0; i < 4; i++)
#pragma unroll
      for (int j = 0; j < 4; j++)
        outb[(size_t)((c0 + tc + i) * 64 + (th + j)) * 64 + w] = acc[i][j];
    __syncthreads();
  }
}

// ---------------------------------------------------------------------------
// outW + epilogue: per (b, h).
// out[c,h,w] = gamma * (out[c,h,w](=outH) + sum_k pv[b,c,h,k]*aW[b,h,w,k]) + v
// ---------------------------------------------------------------------------
__global__ __launch_bounds__(256) void out_w_final_kernel(
    const float* __restrict__ vin, const float* __restrict__ gptr,
    float* __restrict__ out) {
  const int h = blockIdx.x, b = blockIdx.y;
  const float gamma = *gptr;
  __shared__ float A[64][65];    // A[w][k]
  __shared__ float Pv[64][65];   // Pv[c][k]
  const int tid = threadIdx.x;
  for (int i = tid; i < 4096; i += 256) {
    int w = i >> 6, k = i & 63;
    A[w][k] = g_att[(((size_t)(b * 64 + h) * 64 + w) << 7) + 64 + k];
  }
  __syncthreads();
  const int tc = (tid >> 4) * 4;
  const int tw = (tid & 15) * 4;
  const float* pvb = g_pv + (size_t)b * NC * NHW;
  const float* vb = vin + (size_t)b * NC * NHW;
  float* outb = out + (size_t)b * NC * NHW;
  for (int c0 = 0; c0 < NC; c0 += 64) {
    for (int i = tid; i < 4096; i += 256) {
      int cc = i >> 6, k = i & 63;
      Pv[cc][k] = pvb[(size_t)((c0 + cc) * 64 + h) * 64 + k];
    }
    __syncthreads();
    float acc[4][4] = {};
#pragma unroll 4
    for (int k = 0; k < 64; k++) {
      float pvv[4], av[4];
#pragma unroll
      for (int i = 0; i < 4; i++) pvv[i] = Pv[tc + i][k];
#pragma unroll
      for (int j = 0; j < 4; j++) av[j] = A[tw + j][k];
#pragma unroll
      for (int i = 0; i < 4; i++)
#pragma unroll
        for (int j = 0; j < 4; j++) acc[i][j] += pvv[i] * av[j];
    }
#pragma unroll
    for (int i = 0; i < 4; i++) {
      size_t base = (size_t)((c0 + tc + i) * 64 + h) * 64 + tw;
      float4 ov = *(const float4*)(outb + base);
      float4 vv = *(const float4*)(vb + base);
      float4 r;
      r.x = gamma * (ov.x + acc[i][0]) + vv.x;
      r.y = gamma * (ov.y + acc[i][1]) + vv.y;
      r.z = gamma * (ov.z + acc[i][2]) + vv.z;
      r.w = gamma * (ov.w + acc[i][3]) + vv.w;
      *(float4*)(outb + base) = r;
    }
    __syncthreads();
  }
}

// ---------------------------------------------------------------------------
extern "C" void kernel_launch(void* const* d_in, const int* in_sizes, int n_in,
                              void* d_out, int out_size) {
  const float* q  = (const float*)d_in[0];
  const float* k  = (const float*)d_in[1];
  const float* v  = (const float*)d_in[2];
  const float* Wq = (const float*)d_in[3];
  const float* bq = (const float*)d_in[4];
  const float* Wk = (const float*)d_in[5];
  const float* bk = (const float*)d_in[6];
  const float* Wv = (const float*)d_in[7];
  const float* bv = (const float*)d_in[8];
  const float* gm = (const float*)d_in[9];
  float* out = (float*)d_out;

  // Projections: pq, pk (M=64), pv (M=512)
  proj_gemm<<<dim3(32, 1, 8), 256>>>(Wq, bq, q, 64, 0);
  proj_gemm<<<dim3(32, 1, 8), 256>>>(Wk, bk, k, 64, 1);
  proj_gemm<<<dim3(32, 8, 8), 256>>>(Wv, bv, v, 512, 2);

  // Logits + softmax
  logits_h_kernel<<<dim3(64, 8), 256>>>();
  logits_w_kernel<<<dim3(64, 8), 256>>>();
  softmax_kernel<<<4096, 256>>>();

  // Attention outputs + epilogue
  out_h_kernel<<<dim3(64, 8), 256>>>(out);
  out_w_final_kernel<<<dim3(64, 8), 256>>>(v, gm, out);
}

// round 2
// speedup vs baseline: 3.1787x; 3.1787x over previous
#include <cuda_runtime.h>
#include <cuda_bf16.h>
#include <mma.h>
#include <math.h>

using namespace nvcuda;
typedef __nv_bfloat16 bf16;

#define NB 8
#define NC 512
#define NC8 64
#define NHW 4096

#define NEG_INF (__int_as_float(0xff800000))

// Scratch (__device__ globals; allocation-free rule)
__device__ bf16  g_pq[NB * NHW * NC8];   //  4.2 MB  [b][hw][c8]
__device__ bf16  g_pk[NB * NHW * NC8];   //  4.2 MB  [b][hw][c8]
__device__ bf16  g_pv[NB * NHW * NC];    // 33.5 MB  [b][hw][c]
__device__ float g_att[NB * NHW * 128];  // 16.8 MB  [b*hw][128] logits fp32
__device__ bf16  g_attb[NB * NHW * 128]; //  8.4 MB  softmaxed, bf16
__device__ float g_o[NB * NHW * NC];     // 67.1 MB  [b][hw][c] outH+outW fp32

// ---------------------------------------------------------------------------
// Projection GEMM (wmma bf16): P_t[b][n][m] = sum_k W[m][k] * X[b][k][n] + bias[m]
// Block tile 64(m) x 64(n), BK=32, 8 warps (4 m-tiles x 2 n-tiles of 32).
// Output stored channels-last (n-major rows of length M).
// ---------------------------------------------------------------------------
__global__ __launch_bounds__(256) void proj_wmma(
    const float* __restrict__ W, const float* __restrict__ bias,
    const float* __restrict__ X, bf16* __restrict__ P, int M) {
  const int b = blockIdx.z;
  const int n0 = blockIdx.x * 64;
  const int m0 = blockIdx.y * 64;
  __shared__ __align__(32) bf16 As[64][48];   // W tile [m][k]
  __shared__ __align__(32) bf16 Bs[32][72];   // X tile [k][n]
  __shared__ __align__(32) float Cs[64][72];

  const int tid = threadIdx.x;
  const int wid = tid >> 5;
  const int wm = wid & 3;   // m-subtile (16 rows)
  const int wn = wid >> 2;  // n-subtile (32 cols)

  wmma::fragment<wmma::accumulator, 16, 16, 16, float> acc[2];
  wmma::fill_fragment(acc[0], 0.0f);
  wmma::fill_fragment(acc[1], 0.0f);

  const float* Xb = X + (size_t)b * NC * NHW;
  const int am = tid >> 2, ak = (tid & 3) * 8;
  const int bk = tid >> 3, bn = (tid & 7) * 8;

  for (int k0 = 0; k0 < NC; k0 += 32) {
    float4 a0 = *(const float4*)(W + (size_t)(m0 + am) * NC + k0 + ak);
    float4 a1 = *(const float4*)(W + (size_t)(m0 + am) * NC + k0 + ak + 4);
    As[am][ak + 0] = __float2bfloat16(a0.x);
    As[am][ak + 1] = __float2bfloat16(a0.y);
    As[am][ak + 2] = __float2bfloat16(a0.z);
    As[am][ak + 3] = __float2bfloat16(a0.w);
    As[am][ak + 4] = __float2bfloat16(a1.x);
    As[am][ak + 5] = __float2bfloat16(a1.y);
    As[am][ak + 6] = __float2bfloat16(a1.z);
    As[am][ak + 7] = __float2bfloat16(a1.w);
    float4 b0 = *(const float4*)(Xb + (size_t)(k0 + bk) * NHW + n0 + bn);
    float4 b1 = *(const float4*)(Xb + (size_t)(k0 + bk) * NHW + n0 + bn + 4);
    Bs[bk][bn + 0] = __float2bfloat16(b0.x);
    Bs[bk][bn + 1] = __float2bfloat16(b0.y);
    Bs[bk][bn + 2] = __float2bfloat16(b0.z);
    Bs[bk][bn + 3] = __float2bfloat16(b0.w);
    Bs[bk][bn + 4] = __float2bfloat16(b1.x);
    Bs[bk][bn + 5] = __float2bfloat16(b1.y);
    Bs[bk][bn + 6] = __float2bfloat16(b1.z);
    Bs[bk][bn + 7] = __float2bfloat16(b1.w);
    __syncthreads();
#pragma unroll
    for (int kk = 0; kk < 32; kk += 16) {
      wmma::fragment<wmma::matrix_a, 16, 16, 16, bf16, wmma::row_major> af;
      wmma::load_matrix_sync(af, &As[wm * 16][kk], 48);
#pragma unroll
      for (int j = 0; j < 2; j++) {
        wmma::fragment<wmma::matrix_b, 16, 16, 16, bf16, wmma::row_major> bfr;
        wmma::load_matrix_sync(bfr, &Bs[kk][wn * 32 + j * 16], 72);
        wmma::mma_sync(acc[j], af, bfr, acc[j]);
      }
    }
    __syncthreads();
  }

  wmma::store_matrix_sync(&Cs[wm * 16][wn * 32], acc[0], 72, wmma::mem_row_major);
  wmma::store_matrix_sync(&Cs[wm * 16][wn * 32 + 16], acc[1], 72, wmma::mem_row_major);
  __syncthreads();

  // Transposed write: P[b][n0+n][m0+mb..mb+16)
  const int n = tid >> 2, mb = (tid & 3) * 16;
  __align__(16) bf16 outv[16];
#pragma unroll
  for (int i = 0; i < 16; i++)
    outv[i] = __float2bfloat16(Cs[mb + i][n] + bias[m0 + mb + i]);
  bf16* dst = P + ((size_t)b * NHW + n0 + n) * M + m0 + mb;
  *(uint4*)dst = *(uint4*)outv;
  *(uint4*)(dst + 8) = *(uint4*)(outv + 8);
}

// ---------------------------------------------------------------------------
// eH logits (wmma): per (b, w). E[h][k] = sum_c Q[h][c] * K[k][c], diag -inf.
// Q rows = g_pq[b][h*64+w][:], K rows = g_pk[b][k*64+w][:] (c-contiguous).
// ---------------------------------------------------------------------------
__global__ __launch_bounds__(256) void logits_h_wmma() {
  const int w = blockIdx.x, b = blockIdx.y;
  __shared__ __align__(32) bf16 Qs[64][72];
  __shared__ __align__(32) bf16 Ks[64][72];
  __shared__ __align__(32) float Cs[64][68];
  const int tid = threadIdx.x;
  const int r = tid >> 2, cb = (tid & 3) * 16;

  const bf16* qsrc = g_pq + ((size_t)b * NHW + r * 64 + w) * NC8 + cb;
  const bf16* ksrc = g_pk + ((size_t)b * NHW + r * 64 + w) * NC8 + cb;
  *(uint4*)&Qs[r][cb] = *(const uint4*)qsrc;
  *(uint4*)&Qs[r][cb + 8] = *(const uint4*)(qsrc + 8);
  *(uint4*)&Ks[r][cb] = *(const uint4*)ksrc;
  *(uint4*)&Ks[r][cb + 8] = *(const uint4*)(ksrc + 8);
  __syncthreads();

  const int wid = tid >> 5;
  const int wm = wid & 3, wn = wid >> 2;
  wmma::fragment<wmma::accumulator, 16, 16, 16, float> acc[2];
  wmma::fill_fragment(acc[0], 0.0f);
  wmma::fill_fragment(acc[1], 0.0f);
#pragma unroll
  for (int kk = 0; kk < 64; kk += 16) {
    wmma::fragment<wmma::matrix_a, 16, 16, 16, bf16, wmma::row_major> af;
    wmma::load_matrix_sync(af, &Qs[wm * 16][kk], 72);
#pragma unroll
    for (int j = 0; j < 2; j++) {
      wmma::fragment<wmma::matrix_b, 16, 16, 16, bf16, wmma::col_major> bfr;
      wmma::load_matrix_sync(bfr, &Ks[wn * 32 + j * 16][kk], 72);
      wmma::mma_sync(acc[j], af, bfr, acc[j]);
    }
  }
  wmma::store_matrix_sync(&Cs[wm * 16][wn * 32], acc[0], 68, wmma::mem_row_major);
  wmma::store_matrix_sync(&Cs[wm * 16][wn * 32 + 16], acc[1], 68, wmma::mem_row_major);
  __syncthreads();

  const int h = tid >> 2, kb = (tid & 3) * 16;
  float* dst = g_att + (((size_t)(b * 64 + h) * 64 + w) << 7) + kb;
#pragma unroll
  for (int i = 0; i < 16; i += 4) {
    float4 v;
    v.x = (h == kb + i + 0) ? NEG_INF : Cs[h][kb + i + 0];
    v.y = (h == kb + i + 1) ? NEG_INF : Cs[h][kb + i + 1];
    v.z = (h == kb + i + 2) ? NEG_INF : Cs[h][kb + i + 2];
    v.w = (h == kb + i + 3) ? NEG_INF : Cs[h][kb + i + 3];
    *(float4*)(dst + i) = v;
  }
}

// ---------------------------------------------------------------------------
// eW logits (wmma): per (b, h). E[w][k] = sum_c Q[w][c] * K[k][c].
// Tiles are fully contiguous: g_pq[b][h*64 + r][:]
// ---------------------------------------------------------------------------
__global__ __launch_bounds__(256) void logits_w_wmma() {
  const int h = blockIdx.x, b = blockIdx.y;
  __shared__ __align__(32) bf16 Qs[64][72];
  __shared__ __align__(32) bf16 Ks[64][72];
  __shared__ __align__(32) float Cs[64][68];
  const int tid = threadIdx.x;
  const int r = tid >> 2, cb = (tid & 3) * 16;

  const bf16* qsrc = g_pq + ((size_t)b * NHW + h * 64 + r) * NC8 + cb;
  const bf16* ksrc = g_pk + ((size_t)b * NHW + h * 64 + r) * NC8 + cb;
  *(uint4*)&Qs[r][cb] = *(const uint4*)qsrc;
  *(uint4*)&Qs[r][cb + 8] = *(const uint4*)(qsrc + 8);
  *(uint4*)&Ks[r][cb] = *(const uint4*)ksrc;
  *(uint4*)&Ks[r][cb + 8] = *(const uint4*)(ksrc + 8);
  __syncthreads();

  const int wid = tid >> 5;
  const int wm = wid & 3, wn = wid >> 2;
  wmma::fragment<wmma::accumulator, 16, 16, 16, float> acc[2];
  wmma::fill_fragment(acc[0], 0.0f);
  wmma::fill_fragment(acc[1], 0.0f);
#pragma unroll
  for (int kk = 0; kk < 64; kk += 16) {
    wmma::fragment<wmma::matrix_a, 16, 16, 16, bf16, wmma::row_major> af;
    wmma::load_matrix_sync(af, &Qs[wm * 16][kk], 72);
#pragma unroll
    for (int j = 0; j < 2; j++) {
      wmma::fragment<wmma::matrix_b, 16, 16, 16, bf16, wmma::col_major> bfr;
      wmma::load_matrix_sync(bfr, &Ks[wn * 32 + j * 16][kk], 72);
      wmma::mma_sync(acc[j], af, bfr, acc[j]);
    }
  }
  wmma::store_matrix_sync(&Cs[wm * 16][wn * 32], acc[0], 68, wmma::mem_row_major);
  wmma::store_matrix_sync(&Cs[wm * 16][wn * 32 + 16], acc[1], 68, wmma::mem_row_major);
  __syncthreads();

  const int ww = tid >> 2, kb = (tid & 3) * 16;
  float* dst = g_att + (((size_t)(b * 64 + h) * 64 + ww) << 7) + 64 + kb;
#pragma unroll
  for (int i = 0; i < 16; i += 4)
    *(float4*)(dst + i) = *(float4*)&Cs[ww][kb + i];
}

// ---------------------------------------------------------------------------
// Softmax over 128 concatenated logits; one warp per pixel; writes bf16.
// ---------------------------------------------------------------------------
__global__ __launch_bounds__(256) void softmax_kernel() {
  const int row = (blockIdx.x * 256 + threadIdx.x) >> 5;
  const int lane = threadIdx.x & 31;
  const float4* rp = (const float4*)(g_att + (size_t)row * 128);
  float4 v = rp[lane];
  float m = fmaxf(fmaxf(v.x, v.y), fmaxf(v.z, v.w));
#pragma unroll
  for (int o = 16; o; o >>= 1) m = fmaxf(m, __shfl_xor_sync(0xffffffffu, m, o));
  v.x = __expf(v.x - m);
  v.y = __expf(v.y - m);
  v.z = __expf(v.z - m);
  v.w = __expf(v.w - m);
  float s = v.x + v.y + v.z + v.w;
#pragma unroll
  for (int o = 16; o; o >>= 1) s += __shfl_xor_sync(0xffffffffu, s, o);
  float inv = 1.f / s;
  __nv_bfloat162 p0 = __floats2bfloat162_rn(v.x * inv, v.y * inv);
  __nv_bfloat162 p1 = __floats2bfloat162_rn(v.z * inv, v.w * inv);
  uint2 u;
  u.x = *(unsigned*)&p0;
  u.y = *(unsigned*)&p1;
  ((uint2*)(g_attb + (size_t)row * 128))[lane] = u;
}

// ---------------------------------------------------------------------------
// outH (wmma): per (b, w, c-half). O[h][c] = sum_k aH[h][k] * pv[b][k*64+w][c]
// Writes g_o (fp32, channels-last) directly via wmma store (ldm = 64*NC).
// ---------------------------------------------------------------------------
__global__ __launch_bounds__(256) void out_h_wmma() {
  const int ch0 = blockIdx.x * 256;
  const int w = blockIdx.y, b = blockIdx.z;
  __shared__ __align__(32) bf16 As[64][72];
  __shared__ __align__(32) bf16 Vs[64][264];
  const int tid = threadIdx.x;

  {
    const int h = tid >> 2, kb = (tid & 3) * 16;
    const bf16* asrc = g_attb + (((size_t)(b * 64 + h) * 64 + w) << 7) + kb;
    *(uint4*)&As[h][kb] = *(const uint4*)asrc;
    *(uint4*)&As[h][kb + 8] = *(const uint4*)(asrc + 8);
  }
  {
    const int k = tid >> 2, cb = (tid & 3) * 64;
    const bf16* vsrc = g_pv + ((size_t)b * NHW + k * 64 + w) * NC + ch0 + cb;
#pragma unroll
    for (int i = 0; i < 8; i++)
      *(uint4*)&Vs[k][cb + i * 8] = *(const uint4*)(vsrc + i * 8);
  }
  __syncthreads();

  const int wid = tid >> 5;
  const int wh = wid & 1;   // 32 h rows
  const int wc = wid >> 1;  // 64 c cols
  wmma::fragment<wmma::accumulator, 16, 16, 16, float> acc[2][4];
#pragma unroll
  for (int i = 0; i < 2; i++)
#pragma unroll
    for (int j = 0; j < 4; j++) wmma::fill_fragment(acc[i][j], 0.0f);

#pragma unroll
  for (int kk = 0; kk < 64; kk += 16) {
    wmma::fragment<wmma::matrix_a, 16, 16, 16, bf16, wmma::row_major> af[2];
    wmma::load_matrix_sync(af[0], &As[wh * 32][kk], 72);
    wmma::load_matrix_sync(af[1], &As[wh * 32 + 16][kk], 72);
#pragma unroll
    for (int j = 0; j < 4; j++) {
      wmma::fragment<wmma::matrix_b, 16, 16, 16, bf16, wmma::row_major> bfr;
      wmma::load_matrix_sync(bfr, &Vs[kk][wc * 64 + j * 16], 264);
      wmma::mma_sync(acc[0][j], af[0], bfr, acc[0][j]);
      wmma::mma_sync(acc[1][j], af[1], bfr, acc[1][j]);
    }
  }
#pragma unroll
  for (int i = 0; i < 2; i++) {
    const int h = wh * 32 + i * 16;
#pragma unroll
    for (int j = 0; j < 4; j++) {
      float* ptr = g_o + ((size_t)b * NHW + h * 64 + w) * NC + ch0 + wc * 64 + j * 16;
      wmma::store_matrix_sync(ptr, acc[i][j], 64 * NC, wmma::mem_row_major);
    }
  }
}

// ---------------------------------------------------------------------------
// outW (wmma) accumulate: per (b, h, c-half).
// O[w][c] += sum_k aW[w][k] * pv[b][h*64+k][c]; accumulator loaded from g_o.
// ---------------------------------------------------------------------------
__global__ __launch_bounds__(256) void out_w_wmma() {
  const int ch0 = blockIdx.x * 256;
  const int h = blockIdx.y, b = blockIdx.z;
  __shared__ __align__(32) bf16 As[64][72];
  __shared__ __align__(32) bf16 Vs[64][264];
  const int tid = threadIdx.x;

  {
    const int w = tid >> 2, kb = (tid & 3) * 16;
    const bf16* asrc = g_attb + (((size_t)(b * 64 + h) * 64 + w) << 7) + 64 + kb;
    *(uint4*)&As[w][kb] = *(const uint4*)asrc;
    *(uint4*)&As[w][kb + 8] = *(const uint4*)(asrc + 8);
  }
  {
    const int k = tid >> 2, cb = (tid & 3) * 64;
    const bf16* vsrc = g_pv + ((size_t)b * NHW + h * 64 + k) * NC + ch0 + cb;
#pragma unroll
    for (int i = 0; i < 8; i++)
      *(uint4*)&Vs[k][cb + i * 8] = *(const uint4*)(vsrc + i * 8);
  }
  __syncthreads();

  const int wid = tid >> 5;
  const int ww = wid & 1;
  const int wc = wid >> 1;
  wmma::fragment<wmma::accumulator, 16, 16, 16, float> acc[2][4];
#pragma unroll
  for (int i = 0; i < 2; i++)
#pragma unroll
    for (int j = 0; j < 4; j++) {
      float* ptr = g_o + ((size_t)b * NHW + h * 64 + ww * 32 + i * 16) * NC + ch0 + wc * 64 + j * 16;
      wmma::load_matrix_sync(acc[i][j], ptr, NC, wmma::mem_row_major);
    }

#pragma unroll
  for (int kk = 0; kk < 64; kk += 16) {
    wmma::fragment<wmma::matrix_a, 16, 16, 16, bf16, wmma::row_major> af[2];
    wmma::load_matrix_sync(af[0], &As[ww * 32][kk], 72);
    wmma::load_matrix_sync(af[1], &As[ww * 32 + 16][kk], 72);
#pragma unroll
    for (int j = 0; j < 4; j++) {
      wmma::fragment<wmma::matrix_b, 16, 16, 16, bf16, wmma::row_major> bfr;
      wmma::load_matrix_sync(bfr, &Vs[kk][wc * 64 + j * 16], 264);
      wmma::mma_sync(acc[0][j], af[0], bfr, acc[0][j]);
      wmma::mma_sync(acc[1][j], af[1], bfr, acc[1][j]);
    }
  }
#pragma unroll
  for (int i = 0; i < 2; i++)
#pragma unroll
    for (int j = 0; j < 4; j++) {
      float* ptr = g_o + ((size_t)b * NHW + h * 64 + ww * 32 + i * 16) * NC + ch0 + wc * 64 + j * 16;
      wmma::store_matrix_sync(ptr, acc[i][j], NC, wmma::mem_row_major);
    }
}

// ---------------------------------------------------------------------------
// Epilogue: out[b][c][hw] = gamma * g_o[b][hw][c] + v[b][c][hw]  (transpose)
// ---------------------------------------------------------------------------
__global__ __launch_bounds__(256) void epilogue_kernel(
    const float* __restrict__ vin, const float* __restrict__ gptr,
    float* __restrict__ out) {
  const int b = blockIdx.z, c0 = blockIdx.y * 32, p0 = blockIdx.x * 32;
  __shared__ float T[32][33];
  const int tx = threadIdx.x & 31, ty = threadIdx.x >> 5;
  const float gamma = gptr[0];
#pragma unroll
  for (int r = 0; r < 4; r++) {
    const int i = ty + r * 8;
    T[i][tx] = g_o[((size_t)b * NHW + p0 + i) * NC + c0 + tx];
  }
  __syncthreads();
#pragma unroll
  for (int r = 0; r < 4; r++) {
    const int i = ty + r * 8;
    const size_t idx = ((size_t)b * NC + c0 + i) * NHW + p0 + tx;
    out[idx] = gamma * T[tx][i] + vin[idx];
  }
}

// ---------------------------------------------------------------------------
extern "C" void kernel_launch(void* const* d_in, const int* in_sizes, int n_in,
                              void* d_out, int out_size) {
  const float* q  = (const float*)d_in[0];
  const float* k  = (const float*)d_in[1];
  const float* v  = (const float*)d_in[2];
  const float* Wq = (const float*)d_in[3];
  const float* bq = (const float*)d_in[4];
  const float* Wk = (const float*)d_in[5];
  const float* bk = (const float*)d_in[6];
  const float* Wv = (const float*)d_in[7];
  const float* bv = (const float*)d_in[8];
  const float* gm = (const float*)d_in[9];
  float* out = (float*)d_out;

  bf16 *pq_d, *pk_d, *pv_d;
  cudaGetSymbolAddress((void**)&pq_d, g_pq);
  cudaGetSymbolAddress((void**)&pk_d, g_pk);
  cudaGetSymbolAddress((void**)&pv_d, g_pv);

  proj_wmma<<<dim3(64, 1, 8), 256>>>(Wq, bq, q, pq_d, 64);
  proj_wmma<<<dim3(64, 1, 8), 256>>>(Wk, bk, k, pk_d, 64);
  proj_wmma<<<dim3(64, 8, 8), 256>>>(Wv, bv, v, pv_d, 512);

  logits_h_wmma<<<dim3(64, 8), 256>>>();
  logits_w_wmma<<<dim3(64, 8), 256>>>();
  softmax_kernel<<<4096, 256>>>();

  out_h_wmma<<<dim3(2, 64, 8), 256>>>();
  out_w_wmma<<<dim3(2, 64, 8), 256>>>();

  epilogue_kernel<<<dim3(128, 16, 8), 256>>>(v, gm, out);
}

// round 4
// speedup vs baseline: 4.1801x; 1.3150x over previous
#include <cuda_runtime.h>
#include <cuda_bf16.h>
#include <mma.h>
#include <math.h>

using namespace nvcuda;
typedef __nv_bfloat16 bf16;

#define NB 8
#define NC 512
#define NC8 64
#define NHW 4096

#define NEG_INF (__int_as_float(0xff800000))

// Scratch (__device__ globals; allocation-free rule)
__device__ bf16  g_pq[NB * NHW * NC8];   //  4.2 MB  [b][hw][c8]
__device__ bf16  g_pk[NB * NHW * NC8];   //  4.2 MB  [b][hw][c8]
__device__ bf16  g_pv[NB * NHW * NC];    // 33.5 MB  [b][hw][c]
__device__ float g_att[NB * NHW * 128];  // 16.8 MB  logits fp32
__device__ bf16  g_attb[NB * NHW * 128]; //  8.4 MB  softmaxed bf16
__device__ bf16  g_oH[NB * NHW * NC];    // 33.5 MB  outH, bf16, [b][hw][c]

// ---------------------------------------------------------------------------
// Projection GEMM (wmma bf16, reg-prefetch pipelined):
//   P[b][n][m] = sum_k W[m][k] * X[b][k][n] + bias[m]   (channels-last out)
// BM x 128 tile, BK=32. BM=64 (q/k) or 128 (v).
// ---------------------------------------------------------------------------
template <int BM, int M>
__global__ __launch_bounds__(256) void proj_wmma(
    const float* __restrict__ W, const float* __restrict__ bias,
    const float* __restrict__ X, bf16* __restrict__ P) {
  constexpr int BN = 128, BK = 32;
  constexpr int WMW = BM / 32;      // warps along m
  constexpr int WN = BN / (8 / WMW);
  constexpr int FN = WN / 16;
  constexpr int AITER = BM / 64;    // A reg-load iterations (8 floats each)

  __shared__ __align__(16) char smem[34816];
  bf16(*As)[40] = (bf16(*)[40])smem;                          // [BM][40]
  bf16(*Bs)[136] = (bf16(*)[136])(smem + BM * 40 * 2);        // [32][136]
  float(*Cs)[136] = (float(*)[136])smem;                      // [64][136] (aliased)

  const int b = blockIdx.z;
  const int n0 = blockIdx.x * BN;
  const int m0 = blockIdx.y * BM;
  const int tid = threadIdx.x;
  const int wid = tid >> 5;
  const int wm = wid % WMW;
  const int wn = wid / WMW;
  const float* Xb = X + (size_t)b * NC * NHW;

  wmma::fragment<wmma::accumulator, 16, 16, 16, float> acc[2][FN];
#pragma unroll
  for (int i = 0; i < 2; i++)
#pragma unroll
    for (int j = 0; j < FN; j++) wmma::fill_fragment(acc[i][j], 0.0f);

  float4 aR[AITER][2], bR[2][2];

  // prefetch k0 = 0
#pragma unroll
  for (int r = 0; r < AITER; r++) {
    int i = tid + r * 256, row = i >> 2, kb = (i & 3) * 8;
    const float* p = W + (size_t)(m0 + row) * NC + kb;
    aR[r][0] = *(const float4*)p;
    aR[r][1] = *(const float4*)(p + 4);
  }
#pragma unroll
  for (int r = 0; r < 2; r++) {
    int i = tid + r * 256, kr = i >> 4, nb = (i & 15) * 8;
    const float* p = Xb + (size_t)kr * NHW + n0 + nb;
    bR[r][0] = *(const float4*)p;
    bR[r][1] = *(const float4*)(p + 4);
  }

  for (int k0 = 0; k0 < NC; k0 += BK) {
    __syncthreads();
    // store prefetched regs -> smem (fp32 -> bf16)
#pragma unroll
    for (int r = 0; r < AITER; r++) {
      int i = tid + r * 256, row = i >> 2, kb = (i & 3) * 8;
      As[row][kb + 0] = __float2bfloat16(aR[r][0].x);
      As[row][kb + 1] = __float2bfloat16(aR[r][0].y);
      As[row][kb + 2] = __float2bfloat16(aR[r][0].z);
      As[row][kb + 3] = __float2bfloat16(aR[r][0].w);
      As[row][kb + 4] = __float2bfloat16(aR[r][1].x);
      As[row][kb + 5] = __float2bfloat16(aR[r][1].y);
      As[row][kb + 6] = __float2bfloat16(aR[r][1].z);
      As[row][kb + 7] = __float2bfloat16(aR[r][1].w);
    }
#pragma unroll
    for (int r = 0; r < 2; r++) {
      int i = tid + r * 256, kr = i >> 4, nb = (i & 15) * 8;
      Bs[kr][nb + 0] = __float2bfloat16(bR[r][0].x);
      Bs[kr][nb + 1] = __float2bfloat16(bR[r][0].y);
      Bs[kr][nb + 2] = __float2bfloat16(bR[r][0].z);
      Bs[kr][nb + 3] = __float2bfloat16(bR[r][0].w);
      Bs[kr][nb + 4] = __float2bfloat16(bR[r][1].x);
      Bs[kr][nb + 5] = __float2bfloat16(bR[r][1].y);
      Bs[kr][nb + 6] = __float2bfloat16(bR[r][1].z);
      Bs[kr][nb + 7] = __float2bfloat16(bR[r][1].w);
    }
    __syncthreads();
    // prefetch next k-tile while MMAs run
    if (k0 + BK < NC) {
#pragma unroll
      for (int r = 0; r < AITER; r++) {
        int i = tid + r * 256, row = i >> 2, kb = (i & 3) * 8;
        const float* p = W + (size_t)(m0 + row) * NC + k0 + BK + kb;
        aR[r][0] = *(const float4*)p;
        aR[r][1] = *(const float4*)(p + 4);
      }
#pragma unroll
      for (int r = 0; r < 2; r++) {
        int i = tid + r * 256, kr = i >> 4, nb = (i & 15) * 8;
        const float* p = Xb + (size_t)(k0 + BK + kr) * NHW + n0 + nb;
        bR[r][0] = *(const float4*)p;
        bR[r][1] = *(const float4*)(p + 4);
      }
    }
#pragma unroll
    for (int kk = 0; kk < BK; kk += 16) {
      wmma::fragment<wmma::matrix_a, 16, 16, 16, bf16, wmma::row_major> af[2];
      wmma::load_matrix_sync(af[0], &As[wm * 32][kk], 40);
      wmma::load_matrix_sync(af[1], &As[wm * 32 + 16][kk], 40);
#pragma unroll
      for (int fn = 0; fn < FN; fn++) {
        wmma::fragment<wmma::matrix_b, 16, 16, 16, bf16, wmma::row_major> bfr;
        wmma::load_matrix_sync(bfr, &Bs[kk][wn * WN + fn * 16], 136);
        wmma::mma_sync(acc[0][fn], af[0], bfr, acc[0][fn]);
        wmma::mma_sync(acc[1][fn], af[1], bfr, acc[1][fn]);
      }
    }
  }

  // epilogue: stage 64 m-rows at a time, write transposed bf16 with bias
#pragma unroll
  for (int half = 0; half < BM / 64; half++) {
    __syncthreads();
    bool mine = (BM == 64) || ((wm >> 1) == half);
    if (mine) {
      int mloc = (BM == 64) ? wm * 32 : (wm & 1) * 32;
#pragma unroll
      for (int fm = 0; fm < 2; fm++)
#pragma unroll
        for (int fn = 0; fn < FN; fn++)
          wmma::store_matrix_sync(&Cs[mloc + fm * 16][wn * WN + fn * 16],
                                  acc[fm][fn], 136, wmma::mem_row_major);
    }
    __syncthreads();
    const int n = tid >> 1, ml = (tid & 1) * 32;
    const int mg = m0 + half * 64 + ml;
    __align__(16) bf16 ov[32];
#pragma unroll
    for (int i = 0; i < 32; i++)
      ov[i] = __float2bfloat16(Cs[ml + i][n] + bias[mg + i]);
    bf16* dst = P + ((size_t)b * NHW + n0 + n) * M + mg;
#pragma unroll
    for (int i = 0; i < 4; i++) *(uint4*)(dst + i * 8) = *(uint4*)(ov + i * 8);
  }
}

// ---------------------------------------------------------------------------
// eH logits (wmma): per (b, w). E[h][k] = sum_c Q[h][c]*K[k][c]; diag -inf.
// ---------------------------------------------------------------------------
__global__ __launch_bounds__(256) void logits_h_wmma() {
  const int w = blockIdx.x, b = blockIdx.y;
  __shared__ __align__(32) bf16 Qs[64][72];
  __shared__ __align__(32) bf16 Ks[64][72];
  __shared__ __align__(32) float Cs[64][68];
  const int tid = threadIdx.x;
  const int r = tid >> 2, cb = (tid & 3) * 16;

  const bf16* qsrc = g_pq + ((size_t)b * NHW + r * 64 + w) * NC8 + cb;
  const bf16* ksrc = g_pk + ((size_t)b * NHW + r * 64 + w) * NC8 + cb;
  *(uint4*)&Qs[r][cb] = *(const uint4*)qsrc;
  *(uint4*)&Qs[r][cb + 8] = *(const uint4*)(qsrc + 8);
  *(uint4*)&Ks[r][cb] = *(const uint4*)ksrc;
  *(uint4*)&Ks[r][cb + 8] = *(const uint4*)(ksrc + 8);
  __syncthreads();

  const int wid = tid >> 5;
  const int wm = wid & 3, wn = wid >> 2;
  wmma::fragment<wmma::accumulator, 16, 16, 16, float> acc[2];
  wmma::fill_fragment(acc[0], 0.0f);
  wmma::fill_fragment(acc[1], 0.0f);
#pragma unroll
  for (int kk = 0; kk < 64; kk += 16) {
    wmma::fragment<wmma::matrix_a, 16, 16, 16, bf16, wmma::row_major> af;
    wmma::load_matrix_sync(af, &Qs[wm * 16][kk], 72);
#pragma unroll
    for (int j = 0; j < 2; j++) {
      wmma::fragment<wmma::matrix_b, 16, 16, 16, bf16, wmma::col_major> bfr;
      wmma::load_matrix_sync(bfr, &Ks[wn * 32 + j * 16][kk], 72);
      wmma::mma_sync(acc[j], af, bfr, acc[j]);
    }
  }
  wmma::store_matrix_sync(&Cs[wm * 16][wn * 32], acc[0], 68, wmma::mem_row_major);
  wmma::store_matrix_sync(&Cs[wm * 16][wn * 32 + 16], acc[1], 68, wmma::mem_row_major);
  __syncthreads();

  const int h = tid >> 2, kb = (tid & 3) * 16;
  float* dst = g_att + (((size_t)(b * 64 + h) * 64 + w) << 7) + kb;
#pragma unroll
  for (int i = 0; i < 16; i += 4) {
    float4 v;
    v.x = (h == kb + i + 0) ? NEG_INF : Cs[h][kb + i + 0];
    v.y = (h == kb + i + 1) ? NEG_INF : Cs[h][kb + i + 1];
    v.z = (h == kb + i + 2) ? NEG_INF : Cs[h][kb + i + 2];
    v.w = (h == kb + i + 3) ? NEG_INF : Cs[h][kb + i + 3];
    *(float4*)(dst + i) = v;
  }
}

// ---------------------------------------------------------------------------
// eW logits (wmma): per (b, h). E[w][k] = sum_c Q[w][c]*K[k][c].
// ---------------------------------------------------------------------------
__global__ __launch_bounds__(256) void logits_w_wmma() {
  const int h = blockIdx.x, b = blockIdx.y;
  __shared__ __align__(32) bf16 Qs[64][72];
  __shared__ __align__(32) bf16 Ks[64][72];
  __shared__ __align__(32) float Cs[64][68];
  const int tid = threadIdx.x;
  const int r = tid >> 2, cb = (tid & 3) * 16;

  const bf16* qsrc = g_pq + ((size_t)b * NHW + h * 64 + r) * NC8 + cb;
  const bf16* ksrc = g_pk + ((size_t)b * NHW + h * 64 + r) * NC8 + cb;
  *(uint4*)&Qs[r][cb] = *(const uint4*)qsrc;
  *(uint4*)&Qs[r][cb + 8] = *(const uint4*)(qsrc + 8);
  *(uint4*)&Ks[r][cb] = *(const uint4*)ksrc;
  *(uint4*)&Ks[r][cb + 8] = *(const uint4*)(ksrc + 8);
  __syncthreads();

  const int wid = tid >> 5;
  const int wm = wid & 3, wn = wid >> 2;
  wmma::fragment<wmma::accumulator, 16, 16, 16, float> acc[2];
  wmma::fill_fragment(acc[0], 0.0f);
  wmma::fill_fragment(acc[1], 0.0f);
#pragma unroll
  for (int kk = 0; kk < 64; kk += 16) {
    wmma::fragment<wmma::matrix_a, 16, 16, 16, bf16, wmma::row_major> af;
    wmma::load_matrix_sync(af, &Qs[wm * 16][kk], 72);
#pragma unroll
    for (int j = 0; j < 2; j++) {
      wmma::fragment<wmma::matrix_b, 16, 16, 16, bf16, wmma::col_major> bfr;
      wmma::load_matrix_sync(bfr, &Ks[wn * 32 + j * 16][kk], 72);
      wmma::mma_sync(acc[j], af, bfr, acc[j]);
    }
  }
  wmma::store_matrix_sync(&Cs[wm * 16][wn * 32], acc[0], 68, wmma::mem_row_major);
  wmma::store_matrix_sync(&Cs[wm * 16][wn * 32 + 16], acc[1], 68, wmma::mem_row_major);
  __syncthreads();

  const int ww = tid >> 2, kb = (tid & 3) * 16;
  float* dst = g_att + (((size_t)(b * 64 + h) * 64 + ww) << 7) + 64 + kb;
#pragma unroll
  for (int i = 0; i < 16; i += 4)
    *(float4*)(dst + i) = *(float4*)&Cs[ww][kb + i];
}

// ---------------------------------------------------------------------------
// Softmax over 128 concatenated logits; one warp per pixel; writes bf16.
// ---------------------------------------------------------------------------
__global__ __launch_bounds__(256) void softmax_kernel() {
  const int row = (blockIdx.x * 256 + threadIdx.x) >> 5;
  const int lane = threadIdx.x & 31;
  const float4* rp = (const float4*)(g_att + (size_t)row * 128);
  float4 v = rp[lane];
  float m = fmaxf(fmaxf(v.x, v.y), fmaxf(v.z, v.w));
#pragma unroll
  for (int o = 16; o; o >>= 1) m = fmaxf(m, __shfl_xor_sync(0xffffffffu, m, o));
  v.x = __expf(v.x - m);
  v.y = __expf(v.y - m);
  v.z = __expf(v.z - m);
  v.w = __expf(v.w - m);
  float s = v.x + v.y + v.z + v.w;
#pragma unroll
  for (int o = 16; o; o >>= 1) s += __shfl_xor_sync(0xffffffffu, s, o);
  float inv = 1.f / s;
  __nv_bfloat162 p0 = __floats2bfloat162_rn(v.x * inv, v.y * inv);
  __nv_bfloat162 p1 = __floats2bfloat162_rn(v.z * inv, v.w * inv);
  uint2 u;
  u.x = *(unsigned*)&p0;
  u.y = *(unsigned*)&p1;
  ((uint2*)(g_attb + (size_t)row * 128))[lane] = u;
}

// ---------------------------------------------------------------------------
// outH (wmma): per (b, w, c-tile 128). O[h][c] = sum_k aH[h][k]*pv[b][k*64+w][c]
// Written bf16 to g_oH ([b][hw][c]).
// ---------------------------------------------------------------------------
__global__ __launch_bounds__(256) void out_h_wmma() {
  const int ch0 = blockIdx.x * 128;
  const int w = blockIdx.y, b = blockIdx.z;
  __shared__ __align__(16) char smem[34816];
  bf16(*A)[72] = (bf16(*)[72])smem;                 // [64][72]
  bf16(*V)[136] = (bf16(*)[136])(smem + 9216);      // [64][136]
  float(*C)[136] = (float(*)[136])smem;             // aliased
  const int tid = threadIdx.x;

  {
    const int h = tid >> 2, kb = (tid & 3) * 16;
    const bf16* asrc = g_attb + (((size_t)(b * 64 + h) * 64 + w) << 7) + kb;
    *(uint4*)&A[h][kb] = *(const uint4*)asrc;
    *(uint4*)&A[h][kb + 8] = *(const uint4*)(asrc + 8);
  }
  {
    const int k = tid >> 2, cb = (tid & 3) * 32;   // 64 rows x 128 cols exactly
    const bf16* vsrc = g_pv + ((size_t)b * NHW + k * 64 + w) * NC + ch0 + cb;
#pragma unroll
    for (int i = 0; i < 4; i++)
      *(uint4*)&V[k][cb + i * 8] = *(const uint4*)(vsrc + i * 8);
  }
  __syncthreads();

  const int wid = tid >> 5;
  const int wh = wid & 3, wc = wid >> 2;
  wmma::fragment<wmma::accumulator, 16, 16, 16, float> acc[4];
#pragma unroll
  for (int j = 0; j < 4; j++) wmma::fill_fragment(acc[j], 0.0f);
#pragma unroll
  for (int kk = 0; kk < 64; kk += 16) {
    wmma::fragment<wmma::matrix_a, 16, 16, 16, bf16, wmma::row_major> af;
    wmma::load_matrix_sync(af, &A[wh * 16][kk], 72);
#pragma unroll
    for (int fn = 0; fn < 4; fn++) {
      wmma::fragment<wmma::matrix_b, 16, 16, 16, bf16, wmma::row_major> bfr;
      wmma::load_matrix_sync(bfr, &V[kk][wc * 64 + fn * 16], 136);
      wmma::mma_sync(acc[fn], af, bfr, acc[fn]);
    }
  }
  __syncthreads();  // all MMA reads of A/V done before aliasing as C
#pragma unroll
  for (int fn = 0; fn < 4; fn++)
    wmma::store_matrix_sync(&C[wh * 16][wc * 64 + fn * 16], acc[fn], 136,
                            wmma::mem_row_major);
  __syncthreads();

  const int h = tid >> 2, cb = (tid & 3) * 32;
  __align__(16) bf16 ov[32];
#pragma unroll
  for (int i = 0; i < 32; i++) ov[i] = __float2bfloat16(C[h][cb + i]);
  bf16* dst = g_oH + ((size_t)b * NHW + h * 64 + w) * NC + ch0 + cb;
#pragma unroll
  for (int i = 0; i < 4; i++) *(uint4*)(dst + i * 8) = *(uint4*)(ov + i * 8);
}

// ---------------------------------------------------------------------------
// outW + full epilogue: per (b, h, c-tile 128).
// C[w][c] = sum_k aW[w][k]*pv[b][h*64+k][c] + oH[b][h*64+w][c]
// out[b][c][h][w] = gamma*C[w][c] + v[b][c][h][w]   (smem transpose write)
// ---------------------------------------------------------------------------
__global__ __launch_bounds__(256) void out_w_final(
    const float* __restrict__ vin, const float* __restrict__ gptr,
    float* __restrict__ out) {
  const int ch0 = blockIdx.x * 128;
  const int h = blockIdx.y, b = blockIdx.z;
  __shared__ __align__(16) char smem[34816];
  bf16(*A)[72] = (bf16(*)[72])smem;
  bf16(*V)[136] = (bf16(*)[136])(smem + 9216);
  float(*C)[136] = (float(*)[136])smem;
  const int tid = threadIdx.x;

  {
    const int w = tid >> 2, kb = (tid & 3) * 16;
    const bf16* asrc = g_attb + (((size_t)(b * 64 + h) * 64 + w) << 7) + 64 + kb;
    *(uint4*)&A[w][kb] = *(const uint4*)asrc;
    *(uint4*)&A[w][kb + 8] = *(const uint4*)(asrc + 8);
  }
  {
    const int k = tid >> 2, cb = (tid & 3) * 32;   // 64 rows x 128 cols exactly
    const bf16* vsrc = g_pv + ((size_t)b * NHW + h * 64 + k) * NC + ch0 + cb;
#pragma unroll
    for (int i = 0; i < 4; i++)
      *(uint4*)&V[k][cb + i * 8] = *(const uint4*)(vsrc + i * 8);
  }
  __syncthreads();

  const int wid = tid >> 5;
  const int ww = wid & 3, wc = wid >> 2;
  wmma::fragment<wmma::accumulator, 16, 16, 16, float> acc[4];
#pragma unroll
  for (int j = 0; j < 4; j++) wmma::fill_fragment(acc[j], 0.0f);
#pragma unroll
  for (int kk = 0; kk < 64; kk += 16) {
    wmma::fragment<wmma::matrix_a, 16, 16, 16, bf16, wmma::row_major> af;
    wmma::load_matrix_sync(af, &A[ww * 16][kk], 72);
#pragma unroll
    for (int fn = 0; fn < 4; fn++) {
      wmma::fragment<wmma::matrix_b, 16, 16, 16, bf16, wmma::row_major> bfr;
      wmma::load_matrix_sync(bfr, &V[kk][wc * 64 + fn * 16], 136);
      wmma::mma_sync(acc[fn], af, bfr, acc[fn]);
    }
  }
  __syncthreads();
#pragma unroll
  for (int fn = 0; fn < 4; fn++)
    wmma::store_matrix_sync(&C[ww * 16][wc * 64 + fn * 16], acc[fn], 136,
                            wmma::mem_row_major);
  __syncthreads();

  // add outH (bf16, coalesced rows in [w][c] layout)
  {
    const int w = tid >> 2, cb = (tid & 3) * 32;
    const bf16* ohp = g_oH + ((size_t)b * NHW + h * 64 + w) * NC + ch0 + cb;
#pragma unroll
    for (int j = 0; j < 4; j++) {
      uint4 u4 = *(const uint4*)(ohp + j * 8);
      const bf16* e = (const bf16*)&u4;
#pragma unroll
      for (int t = 0; t < 8; t++)
        C[w][cb + j * 8 + t] += __bfloat162float(e[t]);
    }
  }
  __syncthreads();

  // final transposed write: out[b][ch0+c][h][w] = gamma*C[w][c] + v
  const float gamma = gptr[0];
  const int c = tid >> 1, wb = (tid & 1) * 32;
  const size_t base = ((size_t)(b * NC + ch0 + c) * 64 + h) * 64 + wb;
#pragma unroll
  for (int i = 0; i < 32; i += 4) {
    float4 vv = *(const float4*)(vin + base + i);
    float4 r;
    r.x = gamma * C[wb + i + 0][c] + vv.x;
    r.y = gamma * C[wb + i + 1][c] + vv.y;
    r.z = gamma * C[wb + i + 2][c] + vv.z;
    r.w = gamma * C[wb + i + 3][c] + vv.w;
    *(float4*)(out + base + i) = r;
  }
}

// ---------------------------------------------------------------------------
extern "C" void kernel_launch(void* const* d_in, const int* in_sizes, int n_in,
                              void* d_out, int out_size) {
  const float* q  = (const float*)d_in[0];
  const float* k  = (const float*)d_in[1];
  const float* v  = (const float*)d_in[2];
  const float* Wq = (const float*)d_in[3];
  const float* bq = (const float*)d_in[4];
  const float* Wk = (const float*)d_in[5];
  const float* bk = (const float*)d_in[6];
  const float* Wv = (const float*)d_in[7];
  const float* bv = (const float*)d_in[8];
  const float* gm = (const float*)d_in[9];
  float* out = (float*)d_out;

  bf16 *pq_d, *pk_d, *pv_d;
  cudaGetSymbolAddress((void**)&pq_d, g_pq);
  cudaGetSymbolAddress((void**)&pk_d, g_pk);
  cudaGetSymbolAddress((void**)&pv_d, g_pv);

  proj_wmma<64, 64><<<dim3(32, 1, 8), 256>>>(Wq, bq, q, pq_d);
  proj_wmma<64, 64><<<dim3(32, 1, 8), 256>>>(Wk, bk, k, pk_d);
  proj_wmma<128, 512><<<dim3(32, 4, 8), 256>>>(Wv, bv, v, pv_d);

  logits_h_wmma<<<dim3(64, 8), 256>>>();
  logits_w_wmma<<<dim3(64, 8), 256>>>();
  softmax_kernel<<<4096, 256>>>();

  out_h_wmma<<<dim3(4, 64, 8), 256>>>();
  out_w_final<<<dim3(4, 64, 8), 256>>>(v, gm, out);
}